// round 6
// baseline (speedup 1.0000x reference)
#include <cuda_runtime.h>
#include <cstdint>

#define BB 32
#define AA 1024
#define DD 128
#define THR2 0.0025f
#define TMR 64   // MLP rows per block

typedef unsigned long long u64;

// Scratch (allocation-free rule: __device__ globals)
__device__ int      g_cnt[BB * AA];         // per-(batch,group) member counts
__device__ uint32_t g_adj[BB * AA * 32];    // proximity bitmatrix (4MB)
__device__ uint32_t g_members[BB * AA * 32];// per-group member bitmask (4MB)
__device__ int      g_rowlist[BB * AA];     // compacted nonempty group rows
__device__ int      g_nrows;                // count of nonempty rows

__device__ __forceinline__ float gelu_exact(float x) {
    return 0.5f * x * (1.0f + erff(x * 0.70710678118654752f));
}

// ---------------------------------------------------------------------------
// Kernel 1: adjacency bitmatrix, 8 slices x 32 batches = 256 blocks.
// Warp w computes bit-word w (agents j in [32w,32w+32)) — but ONLY for valid
// rows (the scan never reads adjacency rows of invalid agents, and only valid
// agents can start groups). ~50% of rows are invalid -> ~2x fewer ballots.
// Also resets g_nrows (replaces a separate memset launch).
// ---------------------------------------------------------------------------
__global__ __launch_bounds__(1024, 2)
void adj_kernel(const float* __restrict__ coords, const int* __restrict__ mask)
{
    __shared__ float2 sc[AA];
    __shared__ uint32_t sval[4];   // validity of this block's 128 rows

    const int b    = blockIdx.y;
    const int tid  = threadIdx.x;
    const int w    = tid >> 5;
    const int l    = tid & 31;
    const int row0 = blockIdx.x * 128;

    if (tid == 0 && blockIdx.x == 0 && b == 0) g_nrows = 0;

    const float2* gc = (const float2*)(coords + (size_t)b * AA * 2);
    sc[tid] = gc[tid];
    if (w < 4) {   // warps 0-3: validity ballot for rows [row0, row0+128)
        int v = (mask[(size_t)b * AA + row0 + (w << 5) + l] != 0);
        unsigned m = __ballot_sync(0xffffffffu, v);
        if (l == 0) sval[w] = m;
    }
    __syncthreads();

    const float2 cj = sc[(w << 5) + l];
    uint32_t* dst = g_adj + ((size_t)b * AA) * 32 + w;

#pragma unroll
    for (int vw = 0; vw < 4; vw++) {
        unsigned v = sval[vw];
        while (v) {                     // uniform across the warp
            int r = __ffs(v) - 1;
            v &= v - 1u;
            int row = row0 + (vw << 5) + r;
            float2 ci = sc[row];
            float dx = ci.x - cj.x;
            float dy = ci.y - cj.y;
            // match plain (non-fused) evaluation of dx*dx + dy*dy
            float d2 = __fadd_rn(__fmul_rn(dx, dx), __fmul_rn(dy, dy));
            unsigned m = __ballot_sync(0xffffffffu, d2 < THR2);
            if (l == 0) dst[(size_t)row * 32] = m;
        }
    }
}

// ---------------------------------------------------------------------------
// Kernel 2: greedy scan per batch (32 blocks x 1024 threads).
// Bulk-loads the 128KB adjacency slice into SMEM, warp 0 runs the scan and
// stores each group's member bitmask, then the block emits outputs/compaction.
// SMEM: adj 128KB + asg 4KB + cnt 4KB + valid 128B = 136,320 B dynamic.
// ---------------------------------------------------------------------------
__global__ __launch_bounds__(1024, 1)
void scan_kernel(const int* __restrict__ mask,
                 float* __restrict__ out_mask,   // may be null
                 float* __restrict__ out_a2g)    // may be null
{
    extern __shared__ unsigned char sraw[];
    uint32_t* adj     = (uint32_t*)sraw;            // AA*32
    int*      s_asg   = (int*)(adj + AA * 32);      // AA
    int*      s_cnt   = s_asg + AA;                 // AA
    uint32_t* s_valid = (uint32_t*)(s_cnt + AA);    // 32

    const int b   = blockIdx.x;
    const int tid = threadIdx.x;
    const int w   = tid >> 5;
    const int l   = tid & 31;

    // bulk load adjacency slice
    {
        const uint4* src = (const uint4*)(g_adj + (size_t)b * AA * 32);
        uint4* dst = (uint4*)adj;
#pragma unroll
        for (int i = 0; i < 8; i++) dst[tid + i * 1024] = src[tid + i * 1024];
    }
    s_asg[tid] = -1;
    s_cnt[tid] = 0;
    {
        int v = (mask[(size_t)b * AA + tid] != 0);
        unsigned m = __ballot_sync(0xffffffffu, v);
        if (l == 0) s_valid[w] = m;
    }
    __syncthreads();

    // greedy scan on warp 0; lane l owns agents [32l, 32l+32)
    if (w == 0) {
        uint32_t* memb = g_members + ((size_t)b << 10) * 32;
        unsigned U = s_valid[l];
        int gid = 0;
        for (int wdi = 0; wdi < 32; wdi++) {
            unsigned Uw = __shfl_sync(0xffffffffu, U, wdi);
            while (Uw) {
                int bit = __ffs(Uw) - 1;
                int i = (wdi << 5) + bit;
                unsigned take = adj[i * 32 + l] & U;   // includes i itself
                U &= ~take;
                memb[gid * 32 + l] = take;             // member bitmask word l
                unsigned t = take;
                while (t) {
                    int b2 = __ffs(t) - 1;
                    t &= t - 1u;
                    s_asg[(l << 5) + b2] = gid;
                }
                int c = __reduce_add_sync(0xffffffffu, (int)__popc(take));
                if (l == 0) s_cnt[gid] = c;
                gid++;
                Uw = __shfl_sync(0xffffffffu, U, wdi);
            }
        }
    }
    __syncthreads();

    // emit + compact
    {
        int asg = s_asg[tid];
        int cnt = s_cnt[tid];
        g_cnt[(size_t)b * AA + tid] = cnt;
        if (out_a2g)  out_a2g[(size_t)b * AA + tid]  = (float)asg;
        if (out_mask) out_mask[(size_t)b * AA + tid] = (cnt > 0) ? 1.0f : 0.0f;
        if (cnt > 0) {
            int pos = atomicAdd(&g_nrows, 1);
            g_rowlist[pos] = b * AA + tid;
        }
    }
}

// ---------------------------------------------------------------------------
// Kernel 3: fused fill + sparse MLP.
// Grid 512: block bx owns output-row window [64bx, 64bx+64).
//  - FILL: threads <128 compute the constant row gelu(b1)@W2 + b2 and write
//    it to the window's empty rows (cnt==0). Blocks past the compacted-row
//    count do only this (they exit early and free the SM).
//  - MLP: 512 threads, TMR=64 compacted rows, 16 warps x 4 rows each.
//    Pooling fused into x-staging via member-mask gather (no atomics).
//    Weights in SMEM transposed [c][k] with XOR swizzle (conflict-free
//    LDS.128); inner loop uses packed fma.rn.f32x2 (2 FMA/instr).
// SMEM: W1T 64KB + W2T 64KB + x/h 32KB + gb1/srid/scnt = 164,864 B dynamic.
// ---------------------------------------------------------------------------
__global__ __launch_bounds__(512, 1)
void mlp_fill_kernel(const float* __restrict__ emb,
                     const float* __restrict__ W1, const float* __restrict__ b1,
                     const float* __restrict__ W2, const float* __restrict__ b2,
                     float* __restrict__ out)
{
    extern __shared__ float sm[];
    float* sW1T = sm;                  // 16384 floats (4096 float4 slots)
    float* sW2T = sm + 16384;          // 16384
    float* sx   = sm + 32768;          // TMR*DD = 8192
    float* gb1s = sm + 40960;          // 128
    int*   srid = (int*)(sm + 41088);  // 64
    int*   scnt = (int*)(sm + 41152);  // 64

    const int n    = g_nrows;
    const int tid  = threadIdx.x;
    const int base = blockIdx.x * TMR;     // both fill window start & row base
    const bool do_mma = (base < n);

    if (tid < DD) gb1s[tid] = gelu_exact(b1[tid]);
    if (tid < TMR) {
        scnt[tid] = g_cnt[base + tid];
        int idx = base + tid;
        srid[tid] = do_mma ? g_rowlist[idx < n ? idx : n - 1] : 0;
    }

    // stage transposed + swizzled weights: slot(c,g) = c*32 + (g ^ ((c>>2)&7))
    if (do_mma) {
        float4* w1t = (float4*)sW1T;
        float4* w2t = (float4*)sW2T;
#pragma unroll
        for (int it = 0; it < 8; it++) {
            int i = tid + it * 512;
            int c = i & 127, g = i >> 7;
            int slot = c * 32 + (g ^ ((c >> 2) & 7));
            float4 v1, v2;
            v1.x = W1[(4 * g + 0) * DD + c];
            v1.y = W1[(4 * g + 1) * DD + c];
            v1.z = W1[(4 * g + 2) * DD + c];
            v1.w = W1[(4 * g + 3) * DD + c];
            v2.x = W2[(4 * g + 0) * DD + c];
            v2.y = W2[(4 * g + 1) * DD + c];
            v2.z = W2[(4 * g + 2) * DD + c];
            v2.w = W2[(4 * g + 3) * DD + c];
            w1t[slot] = v1;
            w2t[slot] = v2;
        }
    }
    __syncthreads();

    // FILL: constant row for empty groups in this block's window
    if (tid < DD) {
        float a0 = b2[tid], a1 = 0.f, a2 = 0.f, a3 = 0.f;
#pragma unroll 4
        for (int k = 0; k < DD; k += 4) {
            a0 = fmaf(gb1s[k + 0], W2[(k + 0) * DD + tid], a0);
            a1 = fmaf(gb1s[k + 1], W2[(k + 1) * DD + tid], a1);
            a2 = fmaf(gb1s[k + 2], W2[(k + 2) * DD + tid], a2);
            a3 = fmaf(gb1s[k + 3], W2[(k + 3) * DD + tid], a3);
        }
        float cf = (a0 + a1) + (a2 + a3);
        for (int r = 0; r < TMR; r++)
            if (scnt[r] == 0) out[(size_t)(base + r) * DD + tid] = cf;
    }
    if (!do_mma) return;

    const int wp   = tid >> 5;
    const int lane = tid & 31;
    const int r0   = wp * 4;        // 4 rows per warp (16 warps * 4 = 64)
    const int c0   = lane * 4;      // 4 cols per lane
    const int swl  = lane & 7;

    // stage x rows r0..r0+3: gather member rows of each group, mean in regs.
    // Member masks for all 4 rows prefetched up front (overlapped DRAM lat).
    unsigned mw4[4];
    int gr4[4];
#pragma unroll
    for (int rr = 0; rr < 4; rr++) {
        gr4[rr] = srid[r0 + rr];
        mw4[rr] = g_members[(size_t)gr4[rr] * 32 + lane];
    }
#pragma unroll 1
    for (int rr = 0; rr < 4; rr++) {
        const int gr = gr4[rr];
        const unsigned mw = mw4[rr];
        unsigned nz = __ballot_sync(0xffffffffu, mw != 0);
        const float* ebase = emb + (size_t)(gr & ~(AA - 1)) * DD;  // batch base
        float4 a4 = make_float4(0.f, 0.f, 0.f, 0.f);
        while (nz) {
            int w2i = __ffs(nz) - 1;
            nz &= nz - 1u;
            unsigned m = __shfl_sync(0xffffffffu, mw, w2i);
            while (m) {
                int bit = __ffs(m) - 1;
                m &= m - 1u;
                float4 v = *((const float4*)(ebase + (size_t)((w2i << 5) + bit) * DD) + lane);
                a4.x += v.x; a4.y += v.y; a4.z += v.z; a4.w += v.w;
            }
        }
        int c = __reduce_add_sync(0xffffffffu, (int)__popc(mw));
        float inv = 1.0f / (float)(c > 1 ? c : 1);
        a4.x *= inv; a4.y *= inv; a4.z *= inv; a4.w *= inv;
        *(float4*)&sx[(r0 + rr) * DD + c0] = a4;
    }
    __syncwarp();   // warp owns its rows; x within-warp visible

    u64 acc[4][4];

    // ================= layer 1 =================
#pragma unroll
    for (int r = 0; r < 4; r++)
#pragma unroll
        for (int cc = 0; cc < 4; cc++) acc[r][cc] = 0ull;

    {
        const ulonglong2* wp4 = (const ulonglong2*)sW1T;
#pragma unroll 4
        for (int g = 0; g < 32; g++) {
            const int gs = g ^ swl;
            ulonglong2 wv0 = wp4[(c0 + 0) * 32 + gs];
            ulonglong2 wv1 = wp4[(c0 + 1) * 32 + gs];
            ulonglong2 wv2 = wp4[(c0 + 2) * 32 + gs];
            ulonglong2 wv3 = wp4[(c0 + 3) * 32 + gs];
#pragma unroll
            for (int r = 0; r < 4; r++) {
                ulonglong2 xv = *(const ulonglong2*)(sx + (r0 + r) * DD + 4 * g);
                asm("fma.rn.f32x2 %0, %1, %2, %0;" : "+l"(acc[r][0]) : "l"(xv.x), "l"(wv0.x));
                asm("fma.rn.f32x2 %0, %1, %2, %0;" : "+l"(acc[r][1]) : "l"(xv.x), "l"(wv1.x));
                asm("fma.rn.f32x2 %0, %1, %2, %0;" : "+l"(acc[r][2]) : "l"(xv.x), "l"(wv2.x));
                asm("fma.rn.f32x2 %0, %1, %2, %0;" : "+l"(acc[r][3]) : "l"(xv.x), "l"(wv3.x));
                asm("fma.rn.f32x2 %0, %1, %2, %0;" : "+l"(acc[r][0]) : "l"(xv.y), "l"(wv0.y));
                asm("fma.rn.f32x2 %0, %1, %2, %0;" : "+l"(acc[r][1]) : "l"(xv.y), "l"(wv1.y));
                asm("fma.rn.f32x2 %0, %1, %2, %0;" : "+l"(acc[r][2]) : "l"(xv.y), "l"(wv2.y));
                asm("fma.rn.f32x2 %0, %1, %2, %0;" : "+l"(acc[r][3]) : "l"(xv.y), "l"(wv3.y));
            }
        }
    }
    // epilogue 1: h = gelu(lo+hi + b1); warp owns its rows -> no barrier
    {
        float4 bv = *(const float4*)&b1[c0];
#pragma unroll
        for (int r = 0; r < 4; r++) {
            float4 h;
            h.x = gelu_exact(__uint_as_float((unsigned)acc[r][0]) + __uint_as_float((unsigned)(acc[r][0] >> 32)) + bv.x);
            h.y = gelu_exact(__uint_as_float((unsigned)acc[r][1]) + __uint_as_float((unsigned)(acc[r][1] >> 32)) + bv.y);
            h.z = gelu_exact(__uint_as_float((unsigned)acc[r][2]) + __uint_as_float((unsigned)(acc[r][2] >> 32)) + bv.z);
            h.w = gelu_exact(__uint_as_float((unsigned)acc[r][3]) + __uint_as_float((unsigned)(acc[r][3] >> 32)) + bv.w);
            *(float4*)&sx[(r0 + r) * DD + c0] = h;
        }
    }
    __syncwarp();

    // ================= layer 2 =================
#pragma unroll
    for (int r = 0; r < 4; r++)
#pragma unroll
        for (int cc = 0; cc < 4; cc++) acc[r][cc] = 0ull;

    {
        const ulonglong2* wp4 = (const ulonglong2*)sW2T;
#pragma unroll 4
        for (int g = 0; g < 32; g++) {
            const int gs = g ^ swl;
            ulonglong2 wv0 = wp4[(c0 + 0) * 32 + gs];
            ulonglong2 wv1 = wp4[(c0 + 1) * 32 + gs];
            ulonglong2 wv2 = wp4[(c0 + 2) * 32 + gs];
            ulonglong2 wv3 = wp4[(c0 + 3) * 32 + gs];
#pragma unroll
            for (int r = 0; r < 4; r++) {
                ulonglong2 xv = *(const ulonglong2*)(sx + (r0 + r) * DD + 4 * g);
                asm("fma.rn.f32x2 %0, %1, %2, %0;" : "+l"(acc[r][0]) : "l"(xv.x), "l"(wv0.x));
                asm("fma.rn.f32x2 %0, %1, %2, %0;" : "+l"(acc[r][1]) : "l"(xv.x), "l"(wv1.x));
                asm("fma.rn.f32x2 %0, %1, %2, %0;" : "+l"(acc[r][2]) : "l"(xv.x), "l"(wv2.x));
                asm("fma.rn.f32x2 %0, %1, %2, %0;" : "+l"(acc[r][3]) : "l"(xv.x), "l"(wv3.x));
                asm("fma.rn.f32x2 %0, %1, %2, %0;" : "+l"(acc[r][0]) : "l"(xv.y), "l"(wv0.y));
                asm("fma.rn.f32x2 %0, %1, %2, %0;" : "+l"(acc[r][1]) : "l"(xv.y), "l"(wv1.y));
                asm("fma.rn.f32x2 %0, %1, %2, %0;" : "+l"(acc[r][2]) : "l"(xv.y), "l"(wv2.y));
                asm("fma.rn.f32x2 %0, %1, %2, %0;" : "+l"(acc[r][3]) : "l"(xv.y), "l"(wv3.y));
            }
        }
    }
    // epilogue 2: out = lo+hi + b2, scatter to real rows
    {
        float4 bv = *(const float4*)&b2[c0];
#pragma unroll
        for (int r = 0; r < 4; r++) {
            int idx = base + r0 + r;
            if (idx < n) {
                int gr = srid[r0 + r];
                float4 ov;
                ov.x = __uint_as_float((unsigned)acc[r][0]) + __uint_as_float((unsigned)(acc[r][0] >> 32)) + bv.x;
                ov.y = __uint_as_float((unsigned)acc[r][1]) + __uint_as_float((unsigned)(acc[r][1] >> 32)) + bv.y;
                ov.z = __uint_as_float((unsigned)acc[r][2]) + __uint_as_float((unsigned)(acc[r][2] >> 32)) + bv.z;
                ov.w = __uint_as_float((unsigned)acc[r][3]) + __uint_as_float((unsigned)(acc[r][3] >> 32)) + bv.w;
                *(float4*)&out[(size_t)gr * DD + c0] = ov;
            }
        }
    }
}

// ---------------------------------------------------------------------------
extern "C" void kernel_launch(void* const* d_in, const int* in_sizes, int n_in,
                              void* d_out, int out_size)
{
    const float* emb    = (const float*)d_in[0];
    const float* coords = (const float*)d_in[1];
    const int*   mask   = (const int*)d_in[2];
    const float* W1     = (const float*)d_in[3];
    const float* b1     = (const float*)d_in[4];
    const float* W2     = (const float*)d_in[5];
    const float* b2     = (const float*)d_in[6];

    float* out = (float*)d_out;
    const int tok_elems = BB * AA * DD;
    float* out_mask = (out_size >= tok_elems + BB * AA)     ? out + tok_elems           : nullptr;
    float* out_a2g  = (out_size >= tok_elems + 2 * BB * AA) ? out + tok_elems + BB * AA : nullptr;

    const int smem_scan = AA * 32 * 4 + AA * 4 + AA * 4 + 32 * 4;              // 139,392
    const int smem_mlp  = (16384 + 16384 + TMR * DD + DD) * 4 + 2 * TMR * 4;   // 164,864

    cudaFuncSetAttribute(scan_kernel,
                         cudaFuncAttributeMaxDynamicSharedMemorySize, smem_scan);
    cudaFuncSetAttribute(mlp_fill_kernel,
                         cudaFuncAttributeMaxDynamicSharedMemorySize, smem_mlp);

    adj_kernel<<<dim3(8, BB), 1024>>>(coords, mask);
    scan_kernel<<<BB, 1024, smem_scan>>>(mask, out_mask, out_a2g);
    mlp_fill_kernel<<<(BB * AA) / TMR, 512, smem_mlp>>>(emb, W1, b1, W2, b2, out);
}

// round 7
// speedup vs baseline: 1.0450x; 1.0450x over previous
#include <cuda_runtime.h>
#include <cstdint>

#define BB 32
#define AA 1024
#define DD 128
#define THR2 0.0025f
#define TMR 64   // MLP rows per block

typedef unsigned long long u64;

// Scratch (allocation-free rule: __device__ globals)
__device__ int      g_cnt[BB * AA];          // per-(batch,group) member counts
__device__ uint32_t g_adj[BB * AA * 32];     // COMPACTED proximity bitmatrix
__device__ uint32_t g_members[BB * AA * 32]; // per-group ORIGINAL member bitmask
__device__ int      g_ng[BB];                // groups per batch

__device__ __forceinline__ float gelu_exact(float x) {
    return 0.5f * x * (1.0f + erff(x * 0.70710678118654752f));
}

// ---------------------------------------------------------------------------
// Kernel 1: COMPACTED adjacency (valid x valid only, ~4x fewer ballots).
// grid (16, BB): block (x,b) computes compacted rows [64x, 64x+64) vs all
// compacted j. Each block redundantly builds the compact coord list (cheap).
// Warp w handles 2 rows; inner loop over nw j-words with shared cj loads.
// ---------------------------------------------------------------------------
__global__ __launch_bounds__(1024, 1)
void adjc_kernel(const float* __restrict__ coords, const int* __restrict__ mask)
{
    __shared__ float2   scc[AA];    // compacted coords
    __shared__ uint32_t svw[32];    // validity words
    __shared__ int      spre[33];   // exclusive prefix of valid counts
    __shared__ int      s_nv;

    const int b   = blockIdx.y;
    const int tid = threadIdx.x;
    const int w   = tid >> 5;
    const int l   = tid & 31;

    const int v = (mask[(size_t)b * AA + tid] != 0);
    {
        unsigned m = __ballot_sync(0xffffffffu, v);
        if (l == 0) svw[w] = m;
    }
    __syncthreads();
    if (tid < 32) {
        int c = __popc(svw[tid]);
        int x = c;
#pragma unroll
        for (int o = 1; o < 32; o <<= 1) {
            int y = __shfl_up_sync(0xffffffffu, x, o);
            if (tid >= o) x += y;
        }
        spre[tid] = x - c;
        if (tid == 31) s_nv = x;
    }
    __syncthreads();
    const int nv = s_nv;

    // scatter valid coords to compacted slots
    if (v) {
        int cp = spre[w] + __popc(svw[w] & ((1u << l) - 1));
        scc[cp] = ((const float2*)coords)[(size_t)b * AA + tid];
    }
    __syncthreads();

    const int row0 = blockIdx.x * 64;
    if (row0 >= nv) return;
    const int nw = (nv + 31) >> 5;

    const int r0 = row0 + (w << 1);
    const bool h0 = (r0 < nv), h1 = (r0 + 1 < nv);
    const float2 ci0 = scc[h0 ? r0 : 0];
    const float2 ci1 = scc[h1 ? (r0 + 1) : 0];
    uint32_t* dst = g_adj + ((size_t)(b * AA) + r0) * 32;

    for (int word = 0; word < nw; word++) {
        float2 cj = scc[(word << 5) + l];
        float dx0 = ci0.x - cj.x, dy0 = ci0.y - cj.y;
        float d20 = __fadd_rn(__fmul_rn(dx0, dx0), __fmul_rn(dy0, dy0));
        float dx1 = ci1.x - cj.x, dy1 = ci1.y - cj.y;
        float d21 = __fadd_rn(__fmul_rn(dx1, dx1), __fmul_rn(dy1, dy1));
        unsigned m0 = __ballot_sync(0xffffffffu, d20 < THR2);
        unsigned m1 = __ballot_sync(0xffffffffu, d21 < THR2);
        if (l == 0) {
            if (h0) dst[word] = m0;
            if (h1) dst[32 + word] = m1;
        }
    }
}

// ---------------------------------------------------------------------------
// Kernel 2: parallel wavefront clustering (32 blocks x 1024 threads).
// Equivalence to the sequential greedy scan:
//   starter[i]  <=> no earlier valid starter within THR of i
//   asg[j]       =  rank of the minimum-index starter near j (always <= j)
//   cnt[g]       =  |{j : asg[j] = g}|
// Wavefront: compacted agent resolves when (a) an earlier neighbor is a
// starter (-> non-starter), or (b) all earlier neighbors resolved and none
// is a starter (-> starter). Two-barrier snapshot rounds; loop until done.
// SMEM: adj 128KB + cnt 4KB + small = 135,816 B dynamic.
// ---------------------------------------------------------------------------
__global__ __launch_bounds__(1024, 1)
void scan_kernel(const int* __restrict__ mask,
                 float* __restrict__ out_mask,   // may be null
                 float* __restrict__ out_a2g)    // may be null
{
    extern __shared__ unsigned char sraw[];
    uint32_t* adj   = (uint32_t*)sraw;             // AA*32
    int*      s_cnt = (int*)(adj + AA * 32);       // AA
    uint32_t* svw   = (uint32_t*)(s_cnt + AA);     // 32
    uint32_t* sS    = svw + 32;                    // 32 starter bits (compacted)
    uint32_t* sR    = sS + 32;                     // 32 resolved bits (compacted)
    int*      spre  = (int*)(sR + 32);             // 33 valid prefix
    int*      sSp   = spre + 33;                   // 33 starter prefix
    __shared__ int s_nres, s_nv, s_ng;

    const int b   = blockIdx.x;
    const int tid = threadIdx.x;
    const int w   = tid >> 5;
    const int l   = tid & 31;

    const int v = (mask[(size_t)b * AA + tid] != 0);
    {
        unsigned m = __ballot_sync(0xffffffffu, v);
        if (l == 0) svw[w] = m;
    }
    if (tid == 0) s_nres = 0;
    s_cnt[tid] = 0;
    __syncthreads();
    if (tid < 32) {
        int c = __popc(svw[tid]);
        int x = c;
#pragma unroll
        for (int o = 1; o < 32; o <<= 1) {
            int y = __shfl_up_sync(0xffffffffu, x, o);
            if (tid >= o) x += y;
        }
        spre[tid] = x - c;
        if (tid == 31) s_nv = x;
        sS[tid] = 0;
    }
    __syncthreads();
    const int nv = s_nv;

    if (tid < 32) {   // resolved-init: nonexistent compacted slots are resolved
        int rem = nv - (tid << 5);
        unsigned occ = rem >= 32 ? 0xffffffffu : (rem > 0 ? ((1u << rem) - 1) : 0u);
        sR[tid] = ~occ;
    }
    // bulk load compacted adjacency rows [0, nv)
    {
        const uint4* src = (const uint4*)(g_adj + (size_t)b * AA * 32);
        uint4* dst = (uint4*)adj;
        const int tot = nv * 8;
        for (int i = tid; i < tot; i += 1024) dst[i] = src[i];
    }
    __syncthreads();

    // ---- wavefront: thread tid = compacted agent tid (if < nv) ----
    const bool active = (tid < nv);
    const unsigned ebits = (1u << l) - 1;
    unsigned wm = 0;                       // words with earlier neighbors
    if (active) {
        for (int k = 0; k <= w; k++) {
            unsigned a = adj[tid * 32 + k];
            if (k == w) a &= ebits;
            if (a) wm |= 1u << k;
        }
    }
    bool resolved = !active;
    while (true) {
        bool decR = false, decS = false;
        if (!resolved) {
            bool blocked = false, pend = false;
            unsigned t = wm;
            while (t) {
                int k = __ffs(t) - 1;
                t &= t - 1u;
                unsigned a = adj[tid * 32 + k];
                if (k == w) a &= ebits;
                if (a & sS[k]) { blocked = true; break; }
                if (a & ~sR[k]) pend = true;
            }
            if (blocked)      decR = true;
            else if (!pend) { decS = true; decR = true; }
        }
        __syncthreads();   // snapshot reads complete
        unsigned smw = __ballot_sync(0xffffffffu, decS);
        unsigned rmw = __ballot_sync(0xffffffffu, decR);
        if (l == 0 && smw) sS[w] |= smw;
        if (l == 0 && rmw) { sR[w] |= rmw; atomicAdd(&s_nres, __popc(rmw)); }
        if (decR) resolved = true;
        __syncthreads();   // writes visible
        if (s_nres >= nv) break;
    }

    // starter prefix (rank -> group id)
    if (tid < 32) {
        int c = __popc(sS[tid]);
        int x = c;
#pragma unroll
        for (int o = 1; o < 32; o <<= 1) {
            int y = __shfl_up_sync(0xffffffffu, x, o);
            if (tid >= o) x += y;
        }
        sSp[tid] = x - c;
        if (tid == 31) s_ng = x;
    }
    __syncthreads();

    // asg for ORIGINAL agents: rank of first starter in (compacted row & S)
    int asg = -1;
    if (v) {
        int cp = spre[w] + __popc(svw[w] & ebits);
        int cw = cp >> 5;
        for (int k = 0; k <= cw; k++) {
            unsigned m2 = adj[cp * 32 + k] & sS[k];
            if (m2) {
                int bit = __ffs(m2) - 1;
                asg = sSp[k] + __popc(sS[k] & ((1u << bit) - 1));
                break;
            }
        }
    }
    const int ng = s_ng;

    // member masks (original space) + counts via per-warp ballots
    for (int g = 0; g < ng; g++) {
        unsigned mw2 = __ballot_sync(0xffffffffu, asg == g);
        if (l == 0) {
            g_members[((size_t)(b * AA + g)) * 32 + w] = mw2;
            if (mw2) atomicAdd(&s_cnt[g], __popc(mw2));
        }
    }
    __syncthreads();

    // emit
    g_cnt[(size_t)b * AA + tid] = s_cnt[tid];
    if (out_a2g)  out_a2g[(size_t)b * AA + tid]  = (float)asg;
    if (out_mask) out_mask[(size_t)b * AA + tid] = (tid < ng) ? 1.0f : 0.0f;
    if (tid == 0) g_ng[b] = ng;
}

// ---------------------------------------------------------------------------
// Kernel 3: fused fill + sparse MLP. Grid 512 windows of 64 group rows.
// Live rows per window derived from g_ng (groups are contiguous per batch).
// ---------------------------------------------------------------------------
__global__ __launch_bounds__(512, 1)
void mlp_fill_kernel(const float* __restrict__ emb,
                     const float* __restrict__ W1, const float* __restrict__ b1,
                     const float* __restrict__ W2, const float* __restrict__ b2,
                     float* __restrict__ out)
{
    extern __shared__ float sm[];
    float* sW1T = sm;                  // 16384 floats (4096 float4 slots)
    float* sW2T = sm + 16384;          // 16384
    float* sx   = sm + 32768;          // TMR*DD = 8192
    float* gb1s = sm + 40960;          // 128
    int*   srid = (int*)(sm + 41088);  // 64
    int*   scnt = (int*)(sm + 41152);  // 64

    const int tid  = threadIdx.x;
    const int win  = blockIdx.x;
    const int bb   = win >> 4;              // 16 windows per batch
    const int k0   = (win & 15) * TMR;
    const int ng   = g_ng[bb];
    int live = ng - k0;
    if (live > TMR) live = TMR;
    const bool do_mma = (live > 0);
    const int base = win * TMR;             // == bb*AA + k0

    if (tid < DD) gb1s[tid] = gelu_exact(b1[tid]);
    if (tid < TMR) {
        scnt[tid] = g_cnt[base + tid];
        int rc = tid;
        if (rc > live - 1) rc = live - 1;
        if (rc < 0) rc = 0;
        srid[tid] = base + rc;
    }

    // stage transposed + swizzled weights: slot(c,g) = c*32 + (g ^ ((c>>2)&7))
    if (do_mma) {
        float4* w1t = (float4*)sW1T;
        float4* w2t = (float4*)sW2T;
#pragma unroll
        for (int it = 0; it < 8; it++) {
            int i = tid + it * 512;
            int c = i & 127, g = i >> 7;
            int slot = c * 32 + (g ^ ((c >> 2) & 7));
            float4 v1, v2;
            v1.x = W1[(4 * g + 0) * DD + c];
            v1.y = W1[(4 * g + 1) * DD + c];
            v1.z = W1[(4 * g + 2) * DD + c];
            v1.w = W1[(4 * g + 3) * DD + c];
            v2.x = W2[(4 * g + 0) * DD + c];
            v2.y = W2[(4 * g + 1) * DD + c];
            v2.z = W2[(4 * g + 2) * DD + c];
            v2.w = W2[(4 * g + 3) * DD + c];
            w1t[slot] = v1;
            w2t[slot] = v2;
        }
    }
    __syncthreads();

    // FILL: constant row for empty groups in this block's window
    if (tid < DD) {
        float a0 = b2[tid], a1 = 0.f, a2 = 0.f, a3 = 0.f;
#pragma unroll 4
        for (int k = 0; k < DD; k += 4) {
            a0 = fmaf(gb1s[k + 0], W2[(k + 0) * DD + tid], a0);
            a1 = fmaf(gb1s[k + 1], W2[(k + 1) * DD + tid], a1);
            a2 = fmaf(gb1s[k + 2], W2[(k + 2) * DD + tid], a2);
            a3 = fmaf(gb1s[k + 3], W2[(k + 3) * DD + tid], a3);
        }
        float cf = (a0 + a1) + (a2 + a3);
        for (int r = 0; r < TMR; r++)
            if (scnt[r] == 0) out[(size_t)(base + r) * DD + tid] = cf;
    }
    if (!do_mma) return;

    const int wp   = tid >> 5;
    const int lane = tid & 31;
    const int r0   = wp * 4;        // 4 rows per warp (16 warps * 4 = 64)
    const int c0   = lane * 4;      // 4 cols per lane
    const int swl  = lane & 7;

    // stage x rows r0..r0+3: gather member rows of each group, mean in regs.
    unsigned mw4[4];
    int gr4[4];
#pragma unroll
    for (int rr = 0; rr < 4; rr++) {
        gr4[rr] = srid[r0 + rr];
        mw4[rr] = g_members[(size_t)gr4[rr] * 32 + lane];
    }
#pragma unroll 1
    for (int rr = 0; rr < 4; rr++) {
        const int gr = gr4[rr];
        const unsigned mw = mw4[rr];
        unsigned nz = __ballot_sync(0xffffffffu, mw != 0);
        const float* ebase = emb + (size_t)(gr & ~(AA - 1)) * DD;  // batch base
        float4 a4 = make_float4(0.f, 0.f, 0.f, 0.f);
        while (nz) {
            int w2i = __ffs(nz) - 1;
            nz &= nz - 1u;
            unsigned m = __shfl_sync(0xffffffffu, mw, w2i);
            while (m) {
                int bit = __ffs(m) - 1;
                m &= m - 1u;
                float4 v = *((const float4*)(ebase + (size_t)((w2i << 5) + bit) * DD) + lane);
                a4.x += v.x; a4.y += v.y; a4.z += v.z; a4.w += v.w;
            }
        }
        int c = __reduce_add_sync(0xffffffffu, (int)__popc(mw));
        float inv = 1.0f / (float)(c > 1 ? c : 1);
        a4.x *= inv; a4.y *= inv; a4.z *= inv; a4.w *= inv;
        *(float4*)&sx[(r0 + rr) * DD + c0] = a4;
    }
    __syncwarp();   // warp owns its rows; x within-warp visible

    u64 acc[4][4];

    // ================= layer 1 =================
#pragma unroll
    for (int r = 0; r < 4; r++)
#pragma unroll
        for (int cc = 0; cc < 4; cc++) acc[r][cc] = 0ull;

    {
        const ulonglong2* wp4 = (const ulonglong2*)sW1T;
#pragma unroll 4
        for (int g = 0; g < 32; g++) {
            const int gs = g ^ swl;
            ulonglong2 wv0 = wp4[(c0 + 0) * 32 + gs];
            ulonglong2 wv1 = wp4[(c0 + 1) * 32 + gs];
            ulonglong2 wv2 = wp4[(c0 + 2) * 32 + gs];
            ulonglong2 wv3 = wp4[(c0 + 3) * 32 + gs];
#pragma unroll
            for (int r = 0; r < 4; r++) {
                ulonglong2 xv = *(const ulonglong2*)(sx + (r0 + r) * DD + 4 * g);
                asm("fma.rn.f32x2 %0, %1, %2, %0;" : "+l"(acc[r][0]) : "l"(xv.x), "l"(wv0.x));
                asm("fma.rn.f32x2 %0, %1, %2, %0;" : "+l"(acc[r][1]) : "l"(xv.x), "l"(wv1.x));
                asm("fma.rn.f32x2 %0, %1, %2, %0;" : "+l"(acc[r][2]) : "l"(xv.x), "l"(wv2.x));
                asm("fma.rn.f32x2 %0, %1, %2, %0;" : "+l"(acc[r][3]) : "l"(xv.x), "l"(wv3.x));
                asm("fma.rn.f32x2 %0, %1, %2, %0;" : "+l"(acc[r][0]) : "l"(xv.y), "l"(wv0.y));
                asm("fma.rn.f32x2 %0, %1, %2, %0;" : "+l"(acc[r][1]) : "l"(xv.y), "l"(wv1.y));
                asm("fma.rn.f32x2 %0, %1, %2, %0;" : "+l"(acc[r][2]) : "l"(xv.y), "l"(wv2.y));
                asm("fma.rn.f32x2 %0, %1, %2, %0;" : "+l"(acc[r][3]) : "l"(xv.y), "l"(wv3.y));
            }
        }
    }
    // epilogue 1: h = gelu(lo+hi + b1); warp owns its rows -> no barrier
    {
        float4 bv = *(const float4*)&b1[c0];
#pragma unroll
        for (int r = 0; r < 4; r++) {
            float4 h;
            h.x = gelu_exact(__uint_as_float((unsigned)acc[r][0]) + __uint_as_float((unsigned)(acc[r][0] >> 32)) + bv.x);
            h.y = gelu_exact(__uint_as_float((unsigned)acc[r][1]) + __uint_as_float((unsigned)(acc[r][1] >> 32)) + bv.y);
            h.z = gelu_exact(__uint_as_float((unsigned)acc[r][2]) + __uint_as_float((unsigned)(acc[r][2] >> 32)) + bv.z);
            h.w = gelu_exact(__uint_as_float((unsigned)acc[r][3]) + __uint_as_float((unsigned)(acc[r][3] >> 32)) + bv.w);
            *(float4*)&sx[(r0 + r) * DD + c0] = h;
        }
    }
    __syncwarp();

    // ================= layer 2 =================
#pragma unroll
    for (int r = 0; r < 4; r++)
#pragma unroll
        for (int cc = 0; cc < 4; cc++) acc[r][cc] = 0ull;

    {
        const ulonglong2* wp4 = (const ulonglong2*)sW2T;
#pragma unroll 4
        for (int g = 0; g < 32; g++) {
            const int gs = g ^ swl;
            ulonglong2 wv0 = wp4[(c0 + 0) * 32 + gs];
            ulonglong2 wv1 = wp4[(c0 + 1) * 32 + gs];
            ulonglong2 wv2 = wp4[(c0 + 2) * 32 + gs];
            ulonglong2 wv3 = wp4[(c0 + 3) * 32 + gs];
#pragma unroll
            for (int r = 0; r < 4; r++) {
                ulonglong2 xv = *(const ulonglong2*)(sx + (r0 + r) * DD + 4 * g);
                asm("fma.rn.f32x2 %0, %1, %2, %0;" : "+l"(acc[r][0]) : "l"(xv.x), "l"(wv0.x));
                asm("fma.rn.f32x2 %0, %1, %2, %0;" : "+l"(acc[r][1]) : "l"(xv.x), "l"(wv1.x));
                asm("fma.rn.f32x2 %0, %1, %2, %0;" : "+l"(acc[r][2]) : "l"(xv.x), "l"(wv2.x));
                asm("fma.rn.f32x2 %0, %1, %2, %0;" : "+l"(acc[r][3]) : "l"(xv.x), "l"(wv3.x));
                asm("fma.rn.f32x2 %0, %1, %2, %0;" : "+l"(acc[r][0]) : "l"(xv.y), "l"(wv0.y));
                asm("fma.rn.f32x2 %0, %1, %2, %0;" : "+l"(acc[r][1]) : "l"(xv.y), "l"(wv1.y));
                asm("fma.rn.f32x2 %0, %1, %2, %0;" : "+l"(acc[r][2]) : "l"(xv.y), "l"(wv2.y));
                asm("fma.rn.f32x2 %0, %1, %2, %0;" : "+l"(acc[r][3]) : "l"(xv.y), "l"(wv3.y));
            }
        }
    }
    // epilogue 2: out = lo+hi + b2, store live rows
    {
        float4 bv = *(const float4*)&b2[c0];
#pragma unroll
        for (int r = 0; r < 4; r++) {
            if (r0 + r < live) {
                int gr = srid[r0 + r];
                float4 ov;
                ov.x = __uint_as_float((unsigned)acc[r][0]) + __uint_as_float((unsigned)(acc[r][0] >> 32)) + bv.x;
                ov.y = __uint_as_float((unsigned)acc[r][1]) + __uint_as_float((unsigned)(acc[r][1] >> 32)) + bv.y;
                ov.z = __uint_as_float((unsigned)acc[r][2]) + __uint_as_float((unsigned)(acc[r][2] >> 32)) + bv.z;
                ov.w = __uint_as_float((unsigned)acc[r][3]) + __uint_as_float((unsigned)(acc[r][3] >> 32)) + bv.w;
                *(float4*)&out[(size_t)gr * DD + c0] = ov;
            }
        }
    }
}

// ---------------------------------------------------------------------------
extern "C" void kernel_launch(void* const* d_in, const int* in_sizes, int n_in,
                              void* d_out, int out_size)
{
    const float* emb    = (const float*)d_in[0];
    const float* coords = (const float*)d_in[1];
    const int*   mask   = (const int*)d_in[2];
    const float* W1     = (const float*)d_in[3];
    const float* b1     = (const float*)d_in[4];
    const float* W2     = (const float*)d_in[5];
    const float* b2     = (const float*)d_in[6];

    float* out = (float*)d_out;
    const int tok_elems = BB * AA * DD;
    float* out_mask = (out_size >= tok_elems + BB * AA)     ? out + tok_elems           : nullptr;
    float* out_a2g  = (out_size >= tok_elems + 2 * BB * AA) ? out + tok_elems + BB * AA : nullptr;

    const int smem_scan = AA * 32 * 4 + AA * 4 + 3 * 32 * 4 + 2 * 33 * 4;      // 135,816
    const int smem_mlp  = (16384 + 16384 + TMR * DD + DD) * 4 + 2 * TMR * 4;   // 164,864

    cudaFuncSetAttribute(scan_kernel,
                         cudaFuncAttributeMaxDynamicSharedMemorySize, smem_scan);
    cudaFuncSetAttribute(mlp_fill_kernel,
                         cudaFuncAttributeMaxDynamicSharedMemorySize, smem_mlp);

    adjc_kernel<<<dim3(16, BB), 1024>>>(coords, mask);
    scan_kernel<<<BB, 1024, smem_scan>>>(mask, out_mask, out_a2g);
    mlp_fill_kernel<<<(BB * AA) / TMR, 512, smem_mlp>>>(emb, W1, b1, W2, b2, out);
}